// round 14
// baseline (speedup 1.0000x reference)
#include <cuda_runtime.h>
#include <math_constants.h>

// Sampler: B=256 rows, V=128000 vocab.
// inputs: logits [B,V] f32, temperatures [B] f32, uniform_noise [B,V] f32
// output: [tokens (B floats)] ++ [probs (B*V floats)]
//
// 3-kernel split for full-chip occupancy:
//   K1: 512 blocks (4 per row) x 512 thr -> per-block partials in scratch
//   K2: 1 block x 256 thr -> merge partials, token + exponent const per row
//   K3: (8,256) x 256 thr -> probs, reverse segment order for L2 LIFO reuse

#define BB 256
#define VV 128000
#define NV8 (VV / 8)                  // 16000 float8 chunks per row
#define NV4 (VV / 4)                  // 32000 float4 chunks per row
#define SUBB 4                        // sub-blocks per row (K1)
#define NT1 512
#define CH8 (NV8 / SUBB)              // 4000 float8 chunks per sub-block
#define SEGS 8                        // segments per row (K3)
#define NT3 256
#define CH4 (NV4 / SEGS)              // 4000 float4 chunks per segment
#define L2E 1.4426950408889634f
#define LN2 0.6931471805599453f

// scratch (static device globals: allowed, no allocation)
__device__ float g_gv[BB * SUBB];
__device__ int   g_gi[BB * SUBB];
__device__ float g_sv[BB * SUBB];
__device__ int   g_si[BB * SUBB];
__device__ float g_s [BB * SUBB];
__device__ float g_c [BB];

__device__ __forceinline__ float lg2a(float x) {
    float r; asm("lg2.approx.f32 %0, %1;" : "=f"(r) : "f"(x)); return r;
}
__device__ __forceinline__ float ex2a(float x) {
    float r; asm("ex2.approx.f32 %0, %1;" : "=f"(r) : "f"(x)); return r;
}
// 32-byte logits load, pinned toward L2 retention for the K3 reread.
__device__ __forceinline__ void ldg_el8(const float* p, float v[8]) {
    unsigned long long a0, a1, a2, a3;
    asm("ld.global.L2::evict_last.v4.b64 {%0,%1,%2,%3}, [%4];"
        : "=l"(a0), "=l"(a1), "=l"(a2), "=l"(a3) : "l"(p));
    v[0] = __uint_as_float((unsigned)(a0));  v[1] = __uint_as_float((unsigned)(a0 >> 32));
    v[2] = __uint_as_float((unsigned)(a1));  v[3] = __uint_as_float((unsigned)(a1 >> 32));
    v[4] = __uint_as_float((unsigned)(a2));  v[5] = __uint_as_float((unsigned)(a2 >> 32));
    v[6] = __uint_as_float((unsigned)(a3));  v[7] = __uint_as_float((unsigned)(a3 >> 32));
}

// ---------------- K1: pass-1 partials (R8 loop body verbatim) ----------------
__global__ void __launch_bounds__(NT1, 4)
k1_partials(const float* __restrict__ logits,
            const float* __restrict__ temps,
            const float* __restrict__ noise)
{
    const int blk  = blockIdx.x;          // 0..511
    const int b    = blk >> 2;            // row
    const int q    = blk & 3;             // sub-block within row
    const int tid  = threadIdx.x;
    const int lane = tid & 31;
    const int wid  = tid >> 5;            // 0..15

    const float t      = temps[b];
    const float safe_t = (t == 0.0f) ? 1.0f : t;
    const float inv_t  = 1.0f / safe_t;
    const float a      = inv_t * L2E;

    const float* __restrict__ lrow = logits + (size_t)b * VV;
    const float* __restrict__ nrow = noise  + (size_t)b * VV;

    float gv = -CUDART_INF_F; int gi = 0;
    float sv = -CUDART_INF_F; int si = 0;
    float s  = 0.0f;

    const int j0 = q * CH8;
    for (int j = j0 + tid; j < j0 + CH8; j += NT1) {
        float lv[8];
        ldg_el8(lrow + 8 * j, lv);
        #pragma unroll
        for (int h = 0; h < 2; h++) {
            const float4 n4 = __ldcs((const float4*)(nrow + 8 * j) + h);
            const float nv[4] = {n4.x, n4.y, n4.z, n4.w};
            #pragma unroll
            for (int k = 0; k < 4; k++) {
                const int idx = 8 * j + 4 * h + k;
                const float l = lv[4 * h + k];
                const float u = nv[k];
                if (l > gv) {
                    s = s * ex2a((gv - l) * a) + 1.0f;   // exp2(-inf)=0 first time
                    gv = l; gi = idx;
                } else {
                    s += ex2a((l - gv) * a);
                }
                float y = (-LN2) * lg2a(u);
                const float d = 1.0f - u;
                if (u > 0.99f)
                    y = d * fmaf(d, fmaf(d, 0.33333333f, 0.5f), 1.0f);
                const float z = fmaf(lg2a(y), -LN2, l * inv_t);
                if (z > sv) { sv = z; si = idx; }
            }
        }
    }

    // ---- block reduction (two stages) ----
    __shared__ float sh_gv[16]; __shared__ int sh_gi[16];
    __shared__ float sh_sv[16]; __shared__ int sh_si[16];
    __shared__ float sh_sum[16];

    #pragma unroll
    for (int off = 16; off; off >>= 1) {
        float v  = __shfl_xor_sync(0xffffffffu, gv, off);
        int   i  = __shfl_xor_sync(0xffffffffu, gi, off);
        float ws = __shfl_xor_sync(0xffffffffu, s, off);
        if (v > gv) { s = fmaf(s, ex2a((gv - v) * a), ws); gv = v; gi = i; }
        else {
            s = fmaf(ws, ex2a((v - gv) * a), s);
            if (v == gv && i < gi) gi = i;
        }
        float v2 = __shfl_xor_sync(0xffffffffu, sv, off);
        int   i2 = __shfl_xor_sync(0xffffffffu, si, off);
        if (v2 > sv || (v2 == sv && i2 < si)) { sv = v2; si = i2; }
    }
    if (lane == 0) {
        sh_gv[wid] = gv; sh_gi[wid] = gi; sh_sum[wid] = s;
        sh_sv[wid] = sv; sh_si[wid] = si;
    }
    __syncthreads();

    if (wid == 0 && lane < 16) {
        float v = sh_gv[lane]; int i = sh_gi[lane]; float c = sh_sum[lane];
        float v2 = sh_sv[lane]; int i2 = sh_si[lane];
        #pragma unroll
        for (int off = 8; off; off >>= 1) {
            float wv = __shfl_xor_sync(0xffffu, v, off);
            int   wi = __shfl_xor_sync(0xffffu, i, off);
            float wc = __shfl_xor_sync(0xffffu, c, off);
            if (wv > v) { c = fmaf(c, ex2a((v - wv) * a), wc); v = wv; i = wi; }
            else {
                c = fmaf(wc, ex2a((wv - v) * a), c);
                if (wv == v && wi < i) i = wi;
            }
            float wv2 = __shfl_xor_sync(0xffffu, v2, off);
            int   wi2 = __shfl_xor_sync(0xffffu, i2, off);
            if (wv2 > v2 || (wv2 == v2 && wi2 < i2)) { v2 = wv2; i2 = wi2; }
        }
        if (lane == 0) {
            g_gv[blk] = v;  g_gi[blk] = i;  g_s[blk] = c;
            g_sv[blk] = v2; g_si[blk] = i2;
        }
    }
}

// ---------------- K2: merge partials per row ----------------
__global__ void __launch_bounds__(BB)
k2_merge(const float* __restrict__ temps, float* __restrict__ out)
{
    const int b = threadIdx.x;            // 0..255 (one block)
    const float t      = temps[b];
    const float safe_t = (t == 0.0f) ? 1.0f : t;
    const float a      = (1.0f / safe_t) * L2E;

    float v  = g_gv[b * SUBB];  int i  = g_gi[b * SUBB];
    float c  = g_s [b * SUBB];
    float v2 = g_sv[b * SUBB];  int i2 = g_si[b * SUBB];
    #pragma unroll
    for (int q = 1; q < SUBB; q++) {
        const float wv = g_gv[b * SUBB + q]; const int wi = g_gi[b * SUBB + q];
        const float wc = g_s [b * SUBB + q];
        if (wv > v) { c = fmaf(c, ex2a((v - wv) * a), wc); v = wv; i = wi; }
        else {
            c = fmaf(wc, ex2a((wv - v) * a), c);
            if (wv == v && wi < i) i = wi;
        }
        const float wv2 = g_sv[b * SUBB + q]; const int wi2 = g_si[b * SUBB + q];
        if (wv2 > v2 || (wv2 == v2 && wi2 < i2)) { v2 = wv2; i2 = wi2; }
    }
    g_c[b] = fmaf(-v, a, -log2f(c));      // probs exponent constant
    out[b] = (float)((t == 0.0f) ? i : i2);
}

// ---------------- K3: probs (R8 pass-2 body) ----------------
__global__ void __launch_bounds__(NT3)
k3_probs(const float* __restrict__ logits,
         const float* __restrict__ temps,
         float* __restrict__ out)
{
    const int b   = blockIdx.y;
    const int seg = (SEGS - 1) - blockIdx.x;   // reverse: earliest blocks hit row tails
    const int tid = threadIdx.x;

    const float t      = temps[b];
    const float safe_t = (t == 0.0f) ? 1.0f : t;
    const float a      = (1.0f / safe_t) * L2E;
    const float c      = g_c[b];

    const float4* __restrict__ lrow4 = (const float4*)(logits + (size_t)b * VV);
    float4* __restrict__ prow        = (float4*)(out + BB + (size_t)b * VV);

    const int j0 = seg * CH4;
    // x2-unrolled reverse walk within the segment (LIFO within segment too)
    int j = j0 + CH4 - NT3 + tid;
    for (; j >= j0 + NT3; j -= 2 * NT3) {
        const float4 la = lrow4[j];
        const float4 lb = lrow4[j - NT3];
        float4 pa, pb;
        pa.x = ex2a(fmaf(la.x, a, c)); pa.y = ex2a(fmaf(la.y, a, c));
        pa.z = ex2a(fmaf(la.z, a, c)); pa.w = ex2a(fmaf(la.w, a, c));
        pb.x = ex2a(fmaf(lb.x, a, c)); pb.y = ex2a(fmaf(lb.y, a, c));
        pb.z = ex2a(fmaf(lb.z, a, c)); pb.w = ex2a(fmaf(lb.w, a, c));
        __stcs(prow + j, pa);
        __stcs(prow + (j - NT3), pb);
    }
    if (j >= j0) {
        const float4 la = lrow4[j];
        float4 pa;
        pa.x = ex2a(fmaf(la.x, a, c)); pa.y = ex2a(fmaf(la.y, a, c));
        pa.z = ex2a(fmaf(la.z, a, c)); pa.w = ex2a(fmaf(la.w, a, c));
        __stcs(prow + j, pa);
    }
}

extern "C" void kernel_launch(void* const* d_in, const int* in_sizes, int n_in,
                              void* d_out, int out_size) {
    const float* logits = (const float*)d_in[0];
    const float* temps  = (const float*)d_in[1];
    const float* noise  = (const float*)d_in[2];
    float* out = (float*)d_out;

    k1_partials<<<BB * SUBB, NT1>>>(logits, temps, noise);
    k2_merge<<<1, BB>>>(temps, out);
    dim3 g3(SEGS, BB);
    k3_probs<<<g3, NT3>>>(logits, temps, out);
}

// round 16
// speedup vs baseline: 1.1998x; 1.1998x over previous
#include <cuda_runtime.h>
#include <math_constants.h>

// Sampler: B=256 rows, V=128000 vocab.
// inputs: logits [B,V] f32, temperatures [B] f32, uniform_noise [B,V] f32
// output: [tokens (B floats)] ++ [probs (B*V floats)]

#define NT 1024
#define BB 256
#define VV 128000
#define NV8 (VV / 8)                  // 16000 float8 chunks per row (pass 1)
#define NV4 (VV / 4)                  // 32000 float4 chunks per row (pass 2)
#define L2E 1.4426950408889634f
#define LN2 0.6931471805599453f

__device__ __forceinline__ float lg2a(float x) {
    float r; asm("lg2.approx.f32 %0, %1;" : "=f"(r) : "f"(x)); return r;
}
__device__ __forceinline__ float ex2a(float x) {
    float r; asm("ex2.approx.f32 %0, %1;" : "=f"(r) : "f"(x)); return r;
}
// 32-byte logits load, pinned toward L2 retention for the pass-2 reread.
// (sm_103a ptxas requires .v8.b32/.v4.b64 with L2::evict_last)
__device__ __forceinline__ void ldg_el8(const float* p, float v[8]) {
    unsigned long long a0, a1, a2, a3;
    asm("ld.global.L2::evict_last.v4.b64 {%0,%1,%2,%3}, [%4];"
        : "=l"(a0), "=l"(a1), "=l"(a2), "=l"(a3) : "l"(p));
    v[0] = __uint_as_float((unsigned)(a0));  v[1] = __uint_as_float((unsigned)(a0 >> 32));
    v[2] = __uint_as_float((unsigned)(a1));  v[3] = __uint_as_float((unsigned)(a1 >> 32));
    v[4] = __uint_as_float((unsigned)(a2));  v[5] = __uint_as_float((unsigned)(a2 >> 32));
    v[6] = __uint_as_float((unsigned)(a3));  v[7] = __uint_as_float((unsigned)(a3 >> 32));
}

__global__ void __launch_bounds__(NT, 2)   // cap regs at 32 -> 2 blocks/SM
sampler_kernel(const float* __restrict__ logits,
               const float* __restrict__ temps,
               const float* __restrict__ noise,
               float* __restrict__ out)
{
    const int b    = blockIdx.x;
    const int tid  = threadIdx.x;
    const int lane = tid & 31;
    const int wid  = tid >> 5;            // 0..31

    const float t      = temps[b];
    const float safe_t = (t == 0.0f) ? 1.0f : t;
    const float inv_t  = 1.0f / safe_t;
    const float a      = inv_t * L2E;     // logit -> log2-domain scale

    const float* __restrict__ lrow = logits + (size_t)b * VV;
    const float* __restrict__ nrow = noise  + (size_t)b * VV;
    float4* __restrict__ prow      = (float4*)(out + BB + (size_t)b * VV);

    // pass 1 (BRANCHLESS body: no BSSY/BSYNC, pure predication/select):
    //   greedy argmax (gv,gi), online exp-sum s (base = gv), Gumbel argmax (sv,si)
    float gv = -CUDART_INF_F; int gi = 0;
    float sv = -CUDART_INF_F; int si = 0;
    float s  = 0.0f;

    for (int j = tid; j < NV8; j += NT) {
        float lv[8];
        ldg_el8(lrow + 8 * j, lv);
        // consume in two 4-wide halves to keep live ranges small
        #pragma unroll
        for (int h = 0; h < 2; h++) {
            const float4 n4 = __ldcs((const float4*)(nrow + 8 * j) + h);
            const float nv[4] = {n4.x, n4.y, n4.z, n4.w};
            #pragma unroll
            for (int k = 0; k < 4; k++) {
                const int idx = 8 * j + 4 * h + k;
                const float l = lv[4 * h + k];
                const float u = nv[k];
                // branchless online max + sum:
                //   m = max(gv,l); s = s*exp2((gv-m)a) + exp2((l-m)a)
                //   (one factor is exp2(0)=1; first iter gv=-inf -> factor 0)
                const float m  = fmaxf(gv, l);
                const float f  = ex2a((gv - m) * a);
                const float e  = ex2a((l - m) * a);
                s = fmaf(s, f, e);
                gi = (l > gv) ? idx : gi;       // strict > keeps lowest tie idx
                gv = m;
                // Gumbel: y = -log(u); fast LG2, branchless series select for u->1
                const float yl  = lg2a(u);
                const float d   = 1.0f - u;
                const float ser = d * fmaf(d, fmaf(d, 0.33333333f, 0.5f), 1.0f);
                const float y   = (u > 0.99f) ? ser : ((-LN2) * yl);
                const float z   = fmaf(lg2a(y), -LN2, l * inv_t);   // l/t + g
                si = (z > sv) ? idx : si;
                sv = fmaxf(sv, z);
            }
        }
    }

    // ---- block reductions ----
    __shared__ float sh_gv[32]; __shared__ int sh_gi[32];
    __shared__ float sh_sv[32]; __shared__ int sh_si[32];
    __shared__ float sh_sum[32];
    __shared__ float fin_c;

    #pragma unroll
    for (int off = 16; off; off >>= 1) {
        float v  = __shfl_xor_sync(0xffffffffu, gv, off);
        int   i  = __shfl_xor_sync(0xffffffffu, gi, off);
        float ws = __shfl_xor_sync(0xffffffffu, s, off);
        if (v > gv) { s = fmaf(s, ex2a((gv - v) * a), ws); gv = v; gi = i; }
        else {
            s = fmaf(ws, ex2a((v - gv) * a), s);
            if (v == gv && i < gi) gi = i;
        }
        float v2 = __shfl_xor_sync(0xffffffffu, sv, off);
        int   i2 = __shfl_xor_sync(0xffffffffu, si, off);
        if (v2 > sv || (v2 == sv && i2 < si)) { sv = v2; si = i2; }
    }
    if (lane == 0) {
        sh_gv[wid] = gv; sh_gi[wid] = gi; sh_sum[wid] = s;
        sh_sv[wid] = sv; sh_si[wid] = si;
    }
    __syncthreads();

    if (wid == 0) {
        float v = sh_gv[lane]; int i = sh_gi[lane]; float c = sh_sum[lane];
        float v2 = sh_sv[lane]; int i2 = sh_si[lane];
        #pragma unroll
        for (int off = 16; off; off >>= 1) {
            float wv = __shfl_xor_sync(0xffffffffu, v, off);
            int   wi = __shfl_xor_sync(0xffffffffu, i, off);
            float wc = __shfl_xor_sync(0xffffffffu, c, off);
            if (wv > v) { c = fmaf(c, ex2a((v - wv) * a), wc); v = wv; i = wi; }
            else {
                c = fmaf(wc, ex2a((wv - v) * a), c);
                if (wv == v && wi < i) i = wi;
            }
            float wv2 = __shfl_xor_sync(0xffffffffu, v2, off);
            int   wi2 = __shfl_xor_sync(0xffffffffu, i2, off);
            if (wv2 > v2 || (wv2 == v2 && wi2 < i2)) { v2 = wv2; i2 = wi2; }
        }
        if (lane == 0) {
            // probs = exp2(l*a - max*a - log2(sum))
            fin_c = fmaf(-v, a, -log2f(c));
            out[b] = (float)((t == 0.0f) ? i : i2);
        }
    }
    __syncthreads();

    // ---- pass 2: probs = exp2(l*a + c) ----
    // REVERSE order (LIFO): the row tail is the freshest L2 content after
    // pass 1; consuming most-recent-first maximizes hits under LRU.
    // Unrolled x2 for per-thread MLP in the load->EX2->store chain.
    const float c = fin_c;
    const float4* __restrict__ lrow4 = (const float4*)lrow;
    int j = NV4 - NT + tid;               // top chunk for this thread
    for (; j >= NT; j -= 2 * NT) {
        const float4 la = lrow4[j];
        const float4 lb = lrow4[j - NT];
        float4 pa, pb;
        pa.x = ex2a(fmaf(la.x, a, c)); pa.y = ex2a(fmaf(la.y, a, c));
        pa.z = ex2a(fmaf(la.z, a, c)); pa.w = ex2a(fmaf(la.w, a, c));
        pb.x = ex2a(fmaf(lb.x, a, c)); pb.y = ex2a(fmaf(lb.y, a, c));
        pb.z = ex2a(fmaf(lb.z, a, c)); pb.w = ex2a(fmaf(lb.w, a, c));
        __stcs(prow + j, pa);
        __stcs(prow + (j - NT), pb);
    }
    if (j >= 0) {
        const float4 la = lrow4[j];
        float4 pa;
        pa.x = ex2a(fmaf(la.x, a, c)); pa.y = ex2a(fmaf(la.y, a, c));
        pa.z = ex2a(fmaf(la.z, a, c)); pa.w = ex2a(fmaf(la.w, a, c));
        __stcs(prow + j, pa);
    }
}

extern "C" void kernel_launch(void* const* d_in, const int* in_sizes, int n_in,
                              void* d_out, int out_size) {
    const float* logits = (const float*)d_in[0];
    const float* temps  = (const float*)d_in[1];
    const float* noise  = (const float*)d_in[2];
    float* out = (float*)d_out;
    sampler_kernel<<<BB, NT>>>(logits, temps, noise, out);
}